// round 1
// baseline (speedup 1.0000x reference)
#include <cuda_runtime.h>
#include <cuda_bf16.h>

// Problem constants
#define NXS   41
#define GTOT  68921          // 41^3
#define NX2   1681           // 41^2
#define WORDS 2154           // ceil(GTOT/32)
#define KPK   4
#define NEGV  (-1.0e9f)
#define VTH   (-1.0e8f)
#define NPAIR 512            // B*N*C = 1*128*4

// Global sphere bitmask (computed once per launch by init kernel)
__device__ unsigned int g_sphere_bits[WORDS];

// ---------------------------------------------------------------------------
// Kernel 1: compute sphere mask bits from grid_xyz with numpy-identical fp32 ops
// ---------------------------------------------------------------------------
__global__ __launch_bounds__(256) void init_sphere_kernel(const float* __restrict__ grid_xyz)
{
    int g = blockIdx.x * 256 + threadIdx.x;
    bool ok = false;
    if (g < GTOT) {
        float x = grid_xyz[3 * g + 0];
        float y = grid_xyz[3 * g + 1];
        float z = grid_xyz[3 * g + 2];
        // exactly: sqrt((x*x + y*y) + z*z) <= 6.0, fp32, no fma contraction
        float s = __fadd_rn(__fadd_rn(__fmul_rn(x, x), __fmul_rn(y, y)), __fmul_rn(z, z));
        ok = (__fsqrt_rn(s) <= 6.0f);
    }
    unsigned int ballot = __ballot_sync(0xffffffffu, ok);
    if ((threadIdx.x & 31) == 0) {
        int w = g >> 5;
        if (w < WORDS) g_sphere_bits[w] = ballot;
    }
}

// ---------------------------------------------------------------------------
// Kernel 2: per-(n,c) iterative argmax + Chebyshev NMS, then outputs
// ---------------------------------------------------------------------------
__global__ __launch_bounds__(256) void peaks_kernel(
    const float* __restrict__ density,   // [512, G]
    const float* __restrict__ grid_xyz,  // [G, 3]
    const float* __restrict__ Rmats,     // [128, 3, 3]
    const float* __restrict__ tpos,      // [128, 3]
    const float* __restrict__ node_mask, // [128]
    float* __restrict__ out)             // 16384 floats
{
    __shared__ unsigned int smask[WORDS];
    __shared__ float redv[256];
    __shared__ int   redg[256];
    __shared__ float pk_score[KPK];
    __shared__ int   pk_idx[KPK];
    __shared__ int   pk_valid[KPK];
    __shared__ int   cur_i, cur_j, cur_k, cur_valid;

    const int pair = blockIdx.x;            // n*4 + c
    const int tid  = threadIdx.x;
    const float* __restrict__ dens = density + (size_t)pair * GTOT;

    // load sphere bitmask into shared (live mask; bits cleared on suppression)
    for (int w = tid; w < WORDS; w += 256) smask[w] = g_sphere_bits[w];
    __syncthreads();

    const unsigned int mybit = 1u << (tid & 31);
    const int wbase = tid >> 5;

    for (int t = 0; t < KPK; ++t) {
        // ---- strided argmax scan over live mask ----
        float bestv = __int_as_float(0xff800000);   // -inf
        int   bestg = 0;
        int g = tid;
        int w = wbase;
        #pragma unroll 4
        for (int it = 0; it < 270; ++it, g += 256, w += 8) {
            if (g < GTOT) {
                unsigned int mk = smask[w];
                float v = dens[g];
                if ((mk & mybit) && v > bestv) { bestv = v; bestg = g; }
            }
        }

        // ---- block reduce (value desc, index asc tie-break) ----
        redv[tid] = bestv; redg[tid] = bestg;
        __syncthreads();
        for (int s = 128; s > 0; s >>= 1) {
            if (tid < s) {
                float v2 = redv[tid + s]; int g2 = redg[tid + s];
                float v1 = redv[tid];     int g1 = redg[tid];
                if (v2 > v1 || (v2 == v1 && g2 < g1)) { redv[tid] = v2; redg[tid] = g2; }
            }
            __syncthreads();
        }
        if (tid == 0) {
            float sc = redv[0];
            int gi = redg[0];
            int valid = (sc > VTH) ? 1 : 0;
            pk_score[t] = sc;
            pk_idx[t]   = gi;
            pk_valid[t] = valid;
            cur_valid = valid;
            cur_i = gi / NX2;
            cur_j = (gi / NXS) % NXS;
            cur_k = gi % NXS;
        }
        __syncthreads();

        // ---- Chebyshev-ball suppression: clear bits in <=7x7x7 cube ----
        if (t < KPK - 1 && cur_valid) {
            int i0 = max(cur_i - 3, 0), i1 = min(cur_i + 3, NXS - 1);
            int j0 = max(cur_j - 3, 0), j1 = min(cur_j + 3, NXS - 1);
            int k0 = max(cur_k - 3, 0), k1 = min(cur_k + 3, NXS - 1);
            int nj = j1 - j0 + 1;
            int nrows = (i1 - i0 + 1) * nj;
            // rows are >=35 bits apart -> never share a 32-bit word -> no atomics
            for (int r = tid; r < nrows; r += 256) {
                int i = i0 + r / nj;
                int j = j0 + r % nj;
                int gb = i * NX2 + j * NXS + k0;
                int ge = gb + (k1 - k0);
                int w0 = gb >> 5, w1 = ge >> 5;
                unsigned int b0 = (unsigned int)(gb & 31);
                unsigned int b1 = (unsigned int)(ge & 31);
                unsigned int hi = (b1 == 31u) ? 0xffffffffu : ((1u << (b1 + 1)) - 1u);
                if (w0 == w1) {
                    unsigned int m = hi & ~((1u << b0) - 1u);
                    smask[w0] &= ~m;
                } else {
                    smask[w0] &= ((1u << b0) - 1u);
                    smask[w1] &= ~hi;
                }
            }
        }
        __syncthreads();
    }

    // ---- outputs ----
    // layout: coords_local[512*4*3] | coords_global[512*4*3] | scores[512*4] | mask[512*4]
    if (tid < KPK) {
        int k = tid;
        int n = pair >> 2;
        float nm = node_mask[n];
        int valid = pk_valid[k];
        float sc = valid ? pk_score[k] : NEGV;
        float x = 0.0f, y = 0.0f, z = 0.0f;
        if (valid) {
            int gi = pk_idx[k];
            x = grid_xyz[3 * gi + 0];
            y = grid_xyz[3 * gi + 1];
            z = grid_xyz[3 * gi + 2];
        }
        int o = (pair * KPK + k) * 3;
        // coords_local = xyz * node_mask
        out[o + 0] = x * nm;
        out[o + 1] = y * nm;
        out[o + 2] = z * nm;
        // coords_global = (R @ xyz + t) * node_mask
        const float* R  = Rmats + n * 9;
        const float* tp = tpos + n * 3;
        float gx = R[0] * x + R[1] * y + R[2] * z + tp[0];
        float gy = R[3] * x + R[4] * y + R[5] * z + tp[1];
        float gz = R[6] * x + R[7] * y + R[8] * z + tp[2];
        out[6144 + o + 0] = gx * nm;
        out[6144 + o + 1] = gy * nm;
        out[6144 + o + 2] = gz * nm;
        // scores = where(valid, score, NEG) * node_mask
        out[12288 + pair * KPK + k] = sc * nm;
        // mask = valid && (node_mask != 0)
        out[14336 + pair * KPK + k] = (valid && nm != 0.0f) ? 1.0f : 0.0f;
    }
}

extern "C" void kernel_launch(void* const* d_in, const int* in_sizes, int n_in,
                              void* d_out, int out_size)
{
    // metadata order: density, grid_xyz, sphere_mask, coords_int, Rmats, tpos, node_mask
    const float* density   = (const float*)d_in[0];
    const float* grid_xyz  = (const float*)d_in[1];
    const float* Rmats     = (const float*)d_in[4];
    const float* tpos      = (const float*)d_in[5];
    const float* node_mask = (const float*)d_in[6];
    float* out = (float*)d_out;

    init_sphere_kernel<<<(GTOT + 255) / 256, 256>>>(grid_xyz);
    peaks_kernel<<<NPAIR, 256>>>(density, grid_xyz, Rmats, tpos, node_mask, out);
}

// round 2
// speedup vs baseline: 2.2250x; 2.2250x over previous
#include <cuda_runtime.h>
#include <cuda_bf16.h>

// Problem constants
#define NXS   41
#define GTOT  68921          // 41^3
#define NX2   1681           // 41^2
#define WORDS 2154           // ceil(GTOT/32)
#define KPK   4
#define NEGV  (-1.0e9f)
#define VTH   (-1.0e8f)
#define NPAIR 512            // B*N*C = 1*128*4

// Global sphere bitmask (computed once per launch by init kernel)
__device__ unsigned int g_sphere_bits[WORDS];

// ---------------------------------------------------------------------------
// Kernel 1: compute sphere mask bits from grid_xyz with numpy-identical fp32 ops
// ---------------------------------------------------------------------------
__global__ __launch_bounds__(256) void init_sphere_kernel(const float* __restrict__ grid_xyz)
{
    int g = blockIdx.x * 256 + threadIdx.x;
    bool ok = false;
    if (g < GTOT) {
        float x = grid_xyz[3 * g + 0];
        float y = grid_xyz[3 * g + 1];
        float z = grid_xyz[3 * g + 2];
        // exactly: sqrt((x*x + y*y) + z*z) <= 6.0, fp32, no fma contraction
        float s = __fadd_rn(__fadd_rn(__fmul_rn(x, x), __fmul_rn(y, y)), __fmul_rn(z, z));
        ok = (__fsqrt_rn(s) <= 6.0f);
    }
    unsigned int ballot = __ballot_sync(0xffffffffu, ok);
    if ((threadIdx.x & 31) == 0) {
        int w = g >> 5;
        if (w < WORDS) g_sphere_bits[w] = ballot;
    }
}

// order-preserving float->uint key (0 reserved as "masked / -inf")
__device__ __forceinline__ unsigned int f2key(float v)
{
    int i = __float_as_int(v);
    return (unsigned int)(i ^ ((i >> 31) | 0x80000000));
}
__device__ __forceinline__ float key2f(unsigned int k)
{
    int i = (k & 0x80000000u) ? (int)(k ^ 0x80000000u) : (int)~k;
    return __int_as_float(i);
}

// ---------------------------------------------------------------------------
// Kernel 2: per-(n,c) iterative argmax + Chebyshev NMS via chunk-max cache
// ---------------------------------------------------------------------------
__global__ __launch_bounds__(256) void peaks_kernel(
    const float* __restrict__ density,   // [512, G]
    const float* __restrict__ grid_xyz,  // [G, 3]
    const float* __restrict__ Rmats,     // [128, 3, 3]
    const float* __restrict__ tpos,      // [128, 3]
    const float* __restrict__ node_mask, // [128]
    float* __restrict__ out)             // 16384 floats
{
    __shared__ unsigned int smask[WORDS];   // live sphere-and-not-suppressed bits
    __shared__ unsigned int ckey[WORDS];    // per-word max (as monotone uint key)
    __shared__ int          cidx[WORDS];    // per-word argmax global index
    __shared__ unsigned int swk[8];
    __shared__ int          sww[8];
    __shared__ float pk_score[KPK];
    __shared__ int   pk_idx[KPK];
    __shared__ int   pk_valid[KPK];
    __shared__ int   cur_i, cur_j, cur_k, cur_valid;
    __shared__ int   wlist[128];
    __shared__ int   wcount;

    const int pair = blockIdx.x;            // n*4 + c
    const int tid  = threadIdx.x;
    const int lane = tid & 31;
    const int wid  = tid >> 5;
    const float* __restrict__ dens = density + (size_t)pair * GTOT;

    // load sphere bitmask into shared
    for (int w = tid; w < WORDS; w += 256) smask[w] = g_sphere_bits[w];
    __syncthreads();

    // ---- pass 1: per-word masked max + argmax (warp per word) ----
    #pragma unroll 4
    for (int w = wid; w < WORDS; w += 8) {
        unsigned int mk = smask[w];
        unsigned int key = 0;
        if (mk & (1u << lane)) {
            key = f2key(dens[w * 32 + lane]);
        }
        unsigned int m = __reduce_max_sync(0xffffffffu, key);
        unsigned int b = __ballot_sync(0xffffffffu, key == m);
        if (lane == 0) {
            ckey[w] = m;
            cidx[w] = w * 32 + __ffs(b) - 1;
        }
    }
    __syncthreads();

    for (int t = 0; t < KPK; ++t) {
        // ---- argmax over per-word maxima (shared) ----
        unsigned int bk = 0;
        int bw = 0x7FFFFFFF;
        for (int w = tid; w < WORDS; w += 256) {
            unsigned int k = ckey[w];
            if (k > bk) { bk = k; bw = w; }     // ascending scan: lowest w on ties
        }
        unsigned int wm = __reduce_max_sync(0xffffffffu, bk);
        int cand = (bk == wm) ? bw : 0x7FFFFFFF;
        int wmin = (int)__reduce_min_sync(0xffffffffu, (unsigned int)cand);
        if (lane == 0) { swk[wid] = wm; sww[wid] = wmin; }
        __syncthreads();
        if (wid == 0) {
            unsigned int k8 = (lane < 8) ? swk[lane] : 0u;
            int w8 = (lane < 8) ? sww[lane] : 0x7FFFFFFF;
            unsigned int fm = __reduce_max_sync(0xffffffffu, k8);
            int c8 = (k8 == fm) ? w8 : 0x7FFFFFFF;
            int fw = (int)__reduce_min_sync(0xffffffffu, (unsigned int)c8);
            if (lane == 0) {
                float sc = key2f(fm);
                int gi = cidx[fw];
                int valid = (sc > VTH) ? 1 : 0;
                pk_score[t] = sc;
                pk_idx[t]   = gi;
                pk_valid[t] = valid;
                cur_valid = valid;
                cur_i = gi / NX2;
                cur_j = (gi / NXS) % NXS;
                cur_k = gi % NXS;
                wcount = 0;
            }
        }
        __syncthreads();

        if (t < KPK - 1 && cur_valid) {
            // ---- clear bits in <=7x7x7 Chebyshev cube; collect touched words ----
            int i0 = max(cur_i - 3, 0), i1 = min(cur_i + 3, NXS - 1);
            int j0 = max(cur_j - 3, 0), j1 = min(cur_j + 3, NXS - 1);
            int k0 = max(cur_k - 3, 0), k1 = min(cur_k + 3, NXS - 1);
            int nj = j1 - j0 + 1;
            int nrows = (i1 - i0 + 1) * nj;
            // rows are >=35 bits apart -> never share a 32-bit word -> no races
            if (tid < nrows) {
                int i = i0 + tid / nj;
                int j = j0 + tid % nj;
                int gb = i * NX2 + j * NXS + k0;
                int ge = gb + (k1 - k0);
                int w0 = gb >> 5, w1 = ge >> 5;
                unsigned int b0 = (unsigned int)(gb & 31);
                unsigned int b1 = (unsigned int)(ge & 31);
                unsigned int hi = (b1 == 31u) ? 0xffffffffu : ((1u << (b1 + 1)) - 1u);
                int slot;
                if (w0 == w1) {
                    unsigned int m = hi & ~((1u << b0) - 1u);
                    smask[w0] &= ~m;
                    slot = atomicAdd(&wcount, 1);
                    wlist[slot] = w0;
                } else {
                    smask[w0] &= ((1u << b0) - 1u);
                    smask[w1] &= ~hi;
                    slot = atomicAdd(&wcount, 2);
                    wlist[slot] = w0;
                    wlist[slot + 1] = w1;
                }
            }
            __syncthreads();
            // ---- recompute chunk max for touched words (warp per word) ----
            int nw = wcount;
            for (int e = wid; e < nw; e += 8) {
                int w = wlist[e];
                unsigned int mk = smask[w];
                unsigned int key = 0;
                if (mk & (1u << lane)) {
                    key = f2key(dens[w * 32 + lane]);
                }
                unsigned int m = __reduce_max_sync(0xffffffffu, key);
                unsigned int b = __ballot_sync(0xffffffffu, key == m);
                if (lane == 0) {
                    ckey[w] = m;
                    cidx[w] = w * 32 + __ffs(b) - 1;
                }
            }
        }
        __syncthreads();
    }

    // ---- outputs ----
    // layout: coords_local[512*4*3] | coords_global[512*4*3] | scores[512*4] | mask[512*4]
    if (tid < KPK) {
        int k = tid;
        int n = pair >> 2;
        float nm = node_mask[n];
        int valid = pk_valid[k];
        float sc = valid ? pk_score[k] : NEGV;
        float x = 0.0f, y = 0.0f, z = 0.0f;
        if (valid) {
            int gi = pk_idx[k];
            x = grid_xyz[3 * gi + 0];
            y = grid_xyz[3 * gi + 1];
            z = grid_xyz[3 * gi + 2];
        }
        int o = (pair * KPK + k) * 3;
        // coords_local = xyz * node_mask
        out[o + 0] = x * nm;
        out[o + 1] = y * nm;
        out[o + 2] = z * nm;
        // coords_global = (R @ xyz + t) * node_mask
        const float* R  = Rmats + n * 9;
        const float* tp = tpos + n * 3;
        float gx = R[0] * x + R[1] * y + R[2] * z + tp[0];
        float gy = R[3] * x + R[4] * y + R[5] * z + tp[1];
        float gz = R[6] * x + R[7] * y + R[8] * z + tp[2];
        out[6144 + o + 0] = gx * nm;
        out[6144 + o + 1] = gy * nm;
        out[6144 + o + 2] = gz * nm;
        // scores = where(valid, score, NEG) * node_mask
        out[12288 + pair * KPK + k] = sc * nm;
        // mask = valid && (node_mask != 0)
        out[14336 + pair * KPK + k] = (valid && nm != 0.0f) ? 1.0f : 0.0f;
    }
}

extern "C" void kernel_launch(void* const* d_in, const int* in_sizes, int n_in,
                              void* d_out, int out_size)
{
    // metadata order: density, grid_xyz, sphere_mask, coords_int, Rmats, tpos, node_mask
    const float* density   = (const float*)d_in[0];
    const float* grid_xyz  = (const float*)d_in[1];
    const float* Rmats     = (const float*)d_in[4];
    const float* tpos      = (const float*)d_in[5];
    const float* node_mask = (const float*)d_in[6];
    float* out = (float*)d_out;

    init_sphere_kernel<<<(GTOT + 255) / 256, 256>>>(grid_xyz);
    peaks_kernel<<<NPAIR, 256>>>(density, grid_xyz, Rmats, tpos, node_mask, out);
}

// round 3
// speedup vs baseline: 2.5351x; 1.1394x over previous
#include <cuda_runtime.h>
#include <cuda_bf16.h>

// Problem constants
#define NXS   41
#define GTOT  68921          // 41^3
#define NX2   1681           // 41^2
#define WORDS 2154           // ceil(GTOT/32)
#define KPK   4
#define NEGV  (-1.0e9f)
#define VTH   (-1.0e8f)
#define NPAIR 512            // B*N*C = 1*128*4
#define UB    8              // pass-1 pipeline batch (words per warp per iter)
#define NITER 34             // ceil(ceil(WORDS/8)/UB) = ceil(270/8)
#define NMSU  13             // max NMS words per warp (98/8 -> 13)

// Global sphere bitmask (computed once per launch by init kernel)
__device__ unsigned int g_sphere_bits[WORDS];

// ---------------------------------------------------------------------------
// Kernel 1: compute sphere mask bits from grid_xyz with numpy-identical fp32 ops
// ---------------------------------------------------------------------------
__global__ __launch_bounds__(256) void init_sphere_kernel(const float* __restrict__ grid_xyz)
{
    int g = blockIdx.x * 256 + threadIdx.x;
    bool ok = false;
    if (g < GTOT) {
        float x = grid_xyz[3 * g + 0];
        float y = grid_xyz[3 * g + 1];
        float z = grid_xyz[3 * g + 2];
        // exactly: sqrt((x*x + y*y) + z*z) <= 6.0, fp32, no fma contraction
        float s = __fadd_rn(__fadd_rn(__fmul_rn(x, x), __fmul_rn(y, y)), __fmul_rn(z, z));
        ok = (__fsqrt_rn(s) <= 6.0f);
    }
    unsigned int ballot = __ballot_sync(0xffffffffu, ok);
    if ((threadIdx.x & 31) == 0) {
        int w = g >> 5;
        if (w < WORDS) g_sphere_bits[w] = ballot;
    }
}

// order-preserving float->uint key; 0 reserved as "masked"
__device__ __forceinline__ unsigned int f2key(float v)
{
    int i = __float_as_int(v);
    return (unsigned int)(i ^ ((i >> 31) | 0x80000000));
}
__device__ __forceinline__ float key2f(unsigned int k)
{
    int i = (k & 0x80000000u) ? (int)(k ^ 0x80000000u) : (int)~k;
    return __int_as_float(i);
}

// ---------------------------------------------------------------------------
// Kernel 2: per-(n,c) iterative argmax + Chebyshev NMS via chunk-max cache,
//           with explicitly pipelined (double-buffered) global loads.
// ---------------------------------------------------------------------------
__global__ __launch_bounds__(256) void peaks_kernel(
    const float* __restrict__ density,   // [512, G]
    const float* __restrict__ grid_xyz,  // [G, 3]
    const float* __restrict__ Rmats,     // [128, 3, 3]
    const float* __restrict__ tpos,      // [128, 3]
    const float* __restrict__ node_mask, // [128]
    float* __restrict__ out)             // 16384 floats
{
    __shared__ unsigned int smask[WORDS];   // live sphere-and-not-suppressed bits
    __shared__ unsigned int ckey[WORDS];    // per-word max (monotone uint key)
    __shared__ unsigned int swk[8];
    __shared__ int          sww[8];
    __shared__ float pk_score[KPK];
    __shared__ int   pk_idx[KPK];
    __shared__ int   pk_valid[KPK];
    __shared__ int   cur_i, cur_j, cur_k, cur_valid;
    __shared__ int   wlist[128];
    __shared__ int   wcount;

    const int pair = blockIdx.x;            // n*4 + c
    const int tid  = threadIdx.x;
    const int lane = tid & 31;
    const int wid  = tid >> 5;
    const unsigned int mybit = 1u << lane;
    const float* __restrict__ dens = density + (size_t)pair * GTOT;

    // load sphere bitmask into shared
    for (int w = tid; w < WORDS; w += 256) smask[w] = g_sphere_bits[w];
    __syncthreads();

    // ---- pass 1: per-word masked max, double-buffered (MLP = UB per warp) ----
    // word for iter i, slot u: w = wid + 8*(UB*i + u)
    {
        unsigned int keyA[UB];
        #pragma unroll
        for (int u = 0; u < UB; ++u) {
            int w = wid + 8 * u;                     // iter 0, always < WORDS
            keyA[u] = (smask[w] & mybit) ? f2key(__ldg(&dens[w * 32 + lane])) : 0u;
        }
        for (int i = 0; i < NITER; ++i) {
            unsigned int keyB[UB];
            if (i < NITER - 1) {
                #pragma unroll
                for (int u = 0; u < UB; ++u) {
                    int w = wid + 8 * (UB * (i + 1) + u);
                    keyB[u] = (w < WORDS && (smask[w] & mybit))
                            ? f2key(__ldg(&dens[w * 32 + lane])) : 0u;
                }
            }
            #pragma unroll
            for (int u = 0; u < UB; ++u) {
                int w = wid + 8 * (UB * i + u);
                unsigned int m = __reduce_max_sync(0xffffffffu, keyA[u]);
                if (lane == 0 && w < WORDS) ckey[w] = m;
            }
            #pragma unroll
            for (int u = 0; u < UB; ++u) keyA[u] = keyB[u];
        }
    }
    __syncthreads();

    for (int t = 0; t < KPK; ++t) {
        // ---- argmax over per-word maxima (shared) ----
        unsigned int bk = 0;
        int bw = 0x7FFFFFFF;
        for (int w = tid; w < WORDS; w += 256) {
            unsigned int k = ckey[w];
            if (k > bk) { bk = k; bw = w; }     // ascending: lowest w on ties
        }
        unsigned int wm = __reduce_max_sync(0xffffffffu, bk);
        int cand = (bk == wm) ? bw : 0x7FFFFFFF;
        int wmin = (int)__reduce_min_sync(0xffffffffu, (unsigned int)cand);
        if (lane == 0) { swk[wid] = wm; sww[wid] = wmin; }
        __syncthreads();
        if (wid == 0) {
            unsigned int k8 = (lane < 8) ? swk[lane] : 0u;
            int w8 = (lane < 8) ? sww[lane] : 0x7FFFFFFF;
            unsigned int fm = __reduce_max_sync(0xffffffffu, k8);
            int c8 = (k8 == fm) ? w8 : 0x7FFFFFFF;
            int fw = (int)__reduce_min_sync(0xffffffffu, (unsigned int)c8);
            // lazy in-word argmax for the winning word (lowest lane = lowest g)
            unsigned int kk = (smask[fw] & mybit) ? f2key(__ldg(&dens[fw * 32 + lane])) : 0u;
            unsigned int b = __ballot_sync(0xffffffffu, kk == fm);
            if (lane == 0) {
                float sc = key2f(fm);
                int gi = fw * 32 + __ffs(b) - 1;
                int valid = (sc > VTH) ? 1 : 0;
                pk_score[t] = sc;
                pk_idx[t]   = gi;
                pk_valid[t] = valid;
                cur_valid = valid;
                cur_i = gi / NX2;
                cur_j = (gi / NXS) % NXS;
                cur_k = gi % NXS;
                wcount = 0;
            }
        }
        __syncthreads();

        if (t < KPK - 1 && cur_valid) {
            // ---- clear bits in <=7x7x7 Chebyshev cube; collect touched words ----
            int i0 = max(cur_i - 3, 0), i1 = min(cur_i + 3, NXS - 1);
            int j0 = max(cur_j - 3, 0), j1 = min(cur_j + 3, NXS - 1);
            int k0 = max(cur_k - 3, 0), k1 = min(cur_k + 3, NXS - 1);
            int nj = j1 - j0 + 1;
            int nrows = (i1 - i0 + 1) * nj;
            // rows are >=35 bits apart -> never share a 32-bit word -> no races
            if (tid < nrows) {
                int i = i0 + tid / nj;
                int j = j0 + tid % nj;
                int gb = i * NX2 + j * NXS + k0;
                int ge = gb + (k1 - k0);
                int w0 = gb >> 5, w1 = ge >> 5;
                unsigned int b0 = (unsigned int)(gb & 31);
                unsigned int b1 = (unsigned int)(ge & 31);
                unsigned int hi = (b1 == 31u) ? 0xffffffffu : ((1u << (b1 + 1)) - 1u);
                int slot;
                if (w0 == w1) {
                    unsigned int m = hi & ~((1u << b0) - 1u);
                    smask[w0] &= ~m;
                    slot = atomicAdd(&wcount, 1);
                    wlist[slot] = w0;
                } else {
                    smask[w0] &= ((1u << b0) - 1u);
                    smask[w1] &= ~hi;
                    slot = atomicAdd(&wcount, 2);
                    wlist[slot] = w0;
                    wlist[slot + 1] = w1;
                }
            }
            __syncthreads();
            // ---- recompute chunk max for touched words: all loads first (MLP), then reduce ----
            {
                int nw = wcount;
                unsigned int rkey[NMSU];
                int rw[NMSU];
                #pragma unroll
                for (int u = 0; u < NMSU; ++u) {
                    int e = wid + 8 * u;
                    int w = (e < nw) ? wlist[e] : -1;
                    rw[u] = w;
                    rkey[u] = (w >= 0 && (smask[w] & mybit))
                            ? f2key(__ldg(&dens[w * 32 + lane])) : 0u;
                }
                #pragma unroll
                for (int u = 0; u < NMSU; ++u) {
                    if (rw[u] >= 0) {      // uniform across warp
                        unsigned int m = __reduce_max_sync(0xffffffffu, rkey[u]);
                        if (lane == 0) ckey[rw[u]] = m;
                    }
                }
            }
        }
        __syncthreads();
    }

    // ---- outputs ----
    // layout: coords_local[512*4*3] | coords_global[512*4*3] | scores[512*4] | mask[512*4]
    if (tid < KPK) {
        int k = tid;
        int n = pair >> 2;
        float nm = node_mask[n];
        int valid = pk_valid[k];
        float sc = valid ? pk_score[k] : NEGV;
        float x = 0.0f, y = 0.0f, z = 0.0f;
        if (valid) {
            int gi = pk_idx[k];
            x = grid_xyz[3 * gi + 0];
            y = grid_xyz[3 * gi + 1];
            z = grid_xyz[3 * gi + 2];
        }
        int o = (pair * KPK + k) * 3;
        // coords_local = xyz * node_mask
        out[o + 0] = x * nm;
        out[o + 1] = y * nm;
        out[o + 2] = z * nm;
        // coords_global = (R @ xyz + t) * node_mask
        const float* R  = Rmats + n * 9;
        const float* tp = tpos + n * 3;
        float gx = R[0] * x + R[1] * y + R[2] * z + tp[0];
        float gy = R[3] * x + R[4] * y + R[5] * z + tp[1];
        float gz = R[6] * x + R[7] * y + R[8] * z + tp[2];
        out[6144 + o + 0] = gx * nm;
        out[6144 + o + 1] = gy * nm;
        out[6144 + o + 2] = gz * nm;
        // scores = where(valid, score, NEG) * node_mask
        out[12288 + pair * KPK + k] = sc * nm;
        // mask = valid && (node_mask != 0)
        out[14336 + pair * KPK + k] = (valid && nm != 0.0f) ? 1.0f : 0.0f;
    }
}

extern "C" void kernel_launch(void* const* d_in, const int* in_sizes, int n_in,
                              void* d_out, int out_size)
{
    // metadata order: density, grid_xyz, sphere_mask, coords_int, Rmats, tpos, node_mask
    const float* density   = (const float*)d_in[0];
    const float* grid_xyz  = (const float*)d_in[1];
    const float* Rmats     = (const float*)d_in[4];
    const float* tpos      = (const float*)d_in[5];
    const float* node_mask = (const float*)d_in[6];
    float* out = (float*)d_out;

    init_sphere_kernel<<<(GTOT + 255) / 256, 256>>>(grid_xyz);
    peaks_kernel<<<NPAIR, 256>>>(density, grid_xyz, Rmats, tpos, node_mask, out);
}

// round 4
// speedup vs baseline: 6.1948x; 2.4436x over previous
#include <cuda_runtime.h>
#include <cuda_bf16.h>

// Problem constants
#define NXS    41
#define GTOT   68921          // 41^3
#define NX2    1681           // 41^2
#define WORDS  2154           // ceil(GTOT/32)
#define WPAD   2156           // padded word count (multiple of 4)
#define CHUNKS 539            // ceil(GTOT/128)
#define FULLCH 538            // full 128-voxel chunks
#define KPK    4
#define NEGV   (-1.0e9f)
#define VTH    (-1.0e8f)
#define NPAIR  512            // B*N*C = 1*128*4

// Global sphere bitmask (computed once per launch by init kernel)
__device__ unsigned int g_sphere_bits[WORDS];

// ---------------------------------------------------------------------------
// Kernel 1: sphere mask bits from grid_xyz with numpy-identical fp32 ops
// ---------------------------------------------------------------------------
__global__ __launch_bounds__(256) void init_sphere_kernel(const float* __restrict__ grid_xyz)
{
    int g = blockIdx.x * 256 + threadIdx.x;
    bool ok = false;
    if (g < GTOT) {
        float x = grid_xyz[3 * g + 0];
        float y = grid_xyz[3 * g + 1];
        float z = grid_xyz[3 * g + 2];
        float s = __fadd_rn(__fadd_rn(__fmul_rn(x, x), __fmul_rn(y, y)), __fmul_rn(z, z));
        ok = (__fsqrt_rn(s) <= 6.0f);
    }
    unsigned int ballot = __ballot_sync(0xffffffffu, ok);
    if ((threadIdx.x & 31) == 0) {
        int w = g >> 5;
        if (w < WORDS) g_sphere_bits[w] = ballot;
    }
}

// order-preserving float->uint key; 0 reserved as "masked" (below all real keys)
__device__ __forceinline__ unsigned int f2key(float v)
{
    int i = __float_as_int(v);
    return (unsigned int)(i ^ ((i >> 31) | 0x80000000));
}
__device__ __forceinline__ float key2f(unsigned int k)
{
    int i = (k & 0x80000000u) ? (int)(k ^ 0x80000000u) : (int)~k;
    return __int_as_float(i);
}

// ---------------------------------------------------------------------------
// Kernel 2: per-(n,c) iterative argmax + Chebyshev NMS via chunk-max cache.
// Branch-free masked streaming scan; one warp reduction per 128 voxels.
// ---------------------------------------------------------------------------
__global__ __launch_bounds__(256) void peaks_kernel(
    const float* __restrict__ density,   // [512, G]
    const float* __restrict__ grid_xyz,  // [G, 3]
    const float* __restrict__ Rmats,     // [128, 3, 3]
    const float* __restrict__ tpos,      // [128, 3]
    const float* __restrict__ node_mask, // [128]
    float* __restrict__ out)             // 16384 floats
{
    __shared__ unsigned int smask[WPAD];    // live bits (padded tail = 0)
    __shared__ unsigned int ckey[CHUNKS];   // per-128-voxel max (monotone key)
    __shared__ unsigned int swk[8];
    __shared__ int          sww[8];
    __shared__ float pk_score[KPK];
    __shared__ int   pk_idx[KPK];
    __shared__ int   pk_valid[KPK];
    __shared__ int   cur_i, cur_j, cur_k, cur_valid;
    __shared__ int   wlist[128];
    __shared__ int   wcount;

    const int pair = blockIdx.x;            // n*4 + c
    const int tid  = threadIdx.x;
    const int lane = tid & 31;
    const int wid  = tid >> 5;
    const float* __restrict__ dens = density + (size_t)pair * GTOT;

    // load sphere bitmask into shared (padded words -> 0)
    for (int w = tid; w < WPAD; w += 256)
        smask[w] = (w < WORDS) ? g_sphere_bits[w] : 0u;
    __syncthreads();

    // ---- pass 1: per-chunk masked max, branch-free, 4 chunks batched ----
    for (int cb = wid; cb < FULLCH; cb += 32) {
        float        vv[4][4];
        unsigned int mk[4][4];
        #pragma unroll
        for (int b = 0; b < 4; ++b) {
            int c = min(cb + 8 * b, FULLCH - 1);   // tail duplicates chunk 537 (benign)
            #pragma unroll
            for (int u = 0; u < 4; ++u) {
                vv[b][u] = __ldg(&dens[c * 128 + u * 32 + lane]);
                mk[b][u] = smask[c * 4 + u];
            }
        }
        #pragma unroll
        for (int b = 0; b < 4; ++b) {
            unsigned int best = 0;
            #pragma unroll
            for (int u = 0; u < 4; ++u) {
                // sign-extended mask bit: all-ones if lane's bit set, else 0
                unsigned int keep = (unsigned int)(((int)(mk[b][u] << (31 - lane))) >> 31);
                unsigned int key = f2key(vv[b][u]) & keep;
                best = max(best, key);
            }
            unsigned int m = __reduce_max_sync(0xffffffffu, best);
            int c = cb + 8 * b;
            if (lane == 0 && c < FULLCH) ckey[c] = m;
        }
    }
    // epilogue: partial chunk 538 (warp 0, clamped addresses, padded mask bits)
    if (wid == 0) {
        unsigned int best = 0;
        #pragma unroll
        for (int u = 0; u < 4; ++u) {
            int g = FULLCH * 128 + u * 32 + lane;
            int gc = min(g, GTOT - 1);
            unsigned int keep = (unsigned int)(((int)(smask[FULLCH * 4 + u] << (31 - lane))) >> 31);
            unsigned int key = f2key(__ldg(&dens[gc])) & keep;
            best = max(best, key);
        }
        unsigned int m = __reduce_max_sync(0xffffffffu, best);
        if (lane == 0) ckey[FULLCH] = m;
    }
    __syncthreads();

    for (int t = 0; t < KPK; ++t) {
        // ---- argmax over per-chunk maxima ----
        unsigned int bk = 0;
        int bc = 0x7FFFFFFF;
        for (int c = tid; c < CHUNKS; c += 256) {
            unsigned int k = ckey[c];
            if (k > bk) { bk = k; bc = c; }     // ascending: lowest c on ties
        }
        unsigned int wm = __reduce_max_sync(0xffffffffu, bk);
        int cand = (bk == wm) ? bc : 0x7FFFFFFF;
        int wmin = (int)__reduce_min_sync(0xffffffffu, (unsigned int)cand);
        if (lane == 0) { swk[wid] = wm; sww[wid] = wmin; }
        __syncthreads();
        if (wid == 0) {
            unsigned int k8 = (lane < 8) ? swk[lane] : 0u;
            int w8 = (lane < 8) ? sww[lane] : 0x7FFFFFFF;
            unsigned int fm = __reduce_max_sync(0xffffffffu, k8);
            int c8 = (k8 == fm) ? w8 : 0x7FFFFFFF;
            int fc = (int)__reduce_min_sync(0xffffffffu, (unsigned int)c8);
            // lazy in-chunk argmax (lowest g on ties)
            unsigned int bestk = 0;
            int bestg = 0x7FFFFFFF;
            #pragma unroll
            for (int u = 0; u < 4; ++u) {
                int g = fc * 128 + u * 32 + lane;
                int gc = min(g, GTOT - 1);
                unsigned int keep = (unsigned int)(((int)(smask[fc * 4 + u] << (31 - lane))) >> 31);
                unsigned int key = f2key(__ldg(&dens[gc])) & keep;
                if (key > bestk) { bestk = key; bestg = g; }  // ascending u: lowest g
            }
            int cg = (bestk == fm) ? bestg : 0x7FFFFFFF;
            int gi = (int)__reduce_min_sync(0xffffffffu, (unsigned int)cg);
            if (lane == 0) {
                float sc = key2f(fm);
                int valid = (sc > VTH) ? 1 : 0;
                pk_score[t] = sc;
                pk_idx[t]   = gi;
                pk_valid[t] = valid;
                cur_valid = valid;
                cur_i = gi / NX2;
                cur_j = (gi / NXS) % NXS;
                cur_k = gi % NXS;
                wcount = 0;
            }
        }
        __syncthreads();

        if (t < KPK - 1 && cur_valid) {
            // ---- clear bits in <=7x7x7 Chebyshev cube; collect touched chunks ----
            int i0 = max(cur_i - 3, 0), i1 = min(cur_i + 3, NXS - 1);
            int j0 = max(cur_j - 3, 0), j1 = min(cur_j + 3, NXS - 1);
            int k0 = max(cur_k - 3, 0), k1 = min(cur_k + 3, NXS - 1);
            int nj = j1 - j0 + 1;
            int nrows = (i1 - i0 + 1) * nj;
            // rows are >=35 bits apart -> never share a 32-bit word -> no races
            if (tid < nrows) {
                int i = i0 + tid / nj;
                int j = j0 + tid % nj;
                int gb = i * NX2 + j * NXS + k0;
                int ge = gb + (k1 - k0);
                int w0 = gb >> 5, w1 = ge >> 5;
                unsigned int b0 = (unsigned int)(gb & 31);
                unsigned int b1 = (unsigned int)(ge & 31);
                unsigned int hi = (b1 == 31u) ? 0xffffffffu : ((1u << (b1 + 1)) - 1u);
                int slot;
                if (w0 == w1) {
                    unsigned int m = hi & ~((1u << b0) - 1u);
                    smask[w0] &= ~m;
                    slot = atomicAdd(&wcount, 1);
                    wlist[slot] = w0 >> 2;
                } else {
                    smask[w0] &= ((1u << b0) - 1u);
                    smask[w1] &= ~hi;
                    slot = atomicAdd(&wcount, 2);
                    wlist[slot]     = w0 >> 2;
                    wlist[slot + 1] = w1 >> 2;
                }
            }
            __syncthreads();
            // ---- recompute touched chunk maxima (4 entries batched per warp) ----
            {
                int nw = wcount;   // <= 98, entries may repeat (benign)
                for (int e0 = wid; e0 < nw; e0 += 32) {
                    float        vv[4][4];
                    unsigned int mk[4][4];
                    int          cc[4];
                    #pragma unroll
                    for (int b = 0; b < 4; ++b) {
                        int e = e0 + 8 * b;
                        int c = wlist[min(e, nw - 1)];   // dup-clamped
                        cc[b] = (e < nw) ? c : -1;
                        #pragma unroll
                        for (int u = 0; u < 4; ++u) {
                            int g = c * 128 + u * 32 + lane;
                            vv[b][u] = __ldg(&dens[min(g, GTOT - 1)]);
                            mk[b][u] = smask[c * 4 + u];
                        }
                    }
                    #pragma unroll
                    for (int b = 0; b < 4; ++b) {
                        unsigned int best = 0;
                        #pragma unroll
                        for (int u = 0; u < 4; ++u) {
                            unsigned int keep = (unsigned int)(((int)(mk[b][u] << (31 - lane))) >> 31);
                            best = max(best, f2key(vv[b][u]) & keep);
                        }
                        unsigned int m = __reduce_max_sync(0xffffffffu, best);
                        if (lane == 0 && cc[b] >= 0) ckey[cc[b]] = m;
                    }
                }
            }
        }
        __syncthreads();
    }

    // ---- outputs ----
    // layout: coords_local[512*4*3] | coords_global[512*4*3] | scores[512*4] | mask[512*4]
    if (tid < KPK) {
        int k = tid;
        int n = pair >> 2;
        float nm = node_mask[n];
        int valid = pk_valid[k];
        float sc = valid ? pk_score[k] : NEGV;
        float x = 0.0f, y = 0.0f, z = 0.0f;
        if (valid) {
            int gi = pk_idx[k];
            x = grid_xyz[3 * gi + 0];
            y = grid_xyz[3 * gi + 1];
            z = grid_xyz[3 * gi + 2];
        }
        int o = (pair * KPK + k) * 3;
        out[o + 0] = x * nm;
        out[o + 1] = y * nm;
        out[o + 2] = z * nm;
        const float* R  = Rmats + n * 9;
        const float* tp = tpos + n * 3;
        float gx = R[0] * x + R[1] * y + R[2] * z + tp[0];
        float gy = R[3] * x + R[4] * y + R[5] * z + tp[1];
        float gz = R[6] * x + R[7] * y + R[8] * z + tp[2];
        out[6144 + o + 0] = gx * nm;
        out[6144 + o + 1] = gy * nm;
        out[6144 + o + 2] = gz * nm;
        out[12288 + pair * KPK + k] = sc * nm;
        out[14336 + pair * KPK + k] = (valid && nm != 0.0f) ? 1.0f : 0.0f;
    }
}

extern "C" void kernel_launch(void* const* d_in, const int* in_sizes, int n_in,
                              void* d_out, int out_size)
{
    // metadata order: density, grid_xyz, sphere_mask, coords_int, Rmats, tpos, node_mask
    const float* density   = (const float*)d_in[0];
    const float* grid_xyz  = (const float*)d_in[1];
    const float* Rmats     = (const float*)d_in[4];
    const float* tpos      = (const float*)d_in[5];
    const float* node_mask = (const float*)d_in[6];
    float* out = (float*)d_out;

    init_sphere_kernel<<<(GTOT + 255) / 256, 256>>>(grid_xyz);
    peaks_kernel<<<NPAIR, 256>>>(density, grid_xyz, Rmats, tpos, node_mask, out);
}